// round 2
// baseline (speedup 1.0000x reference)
#include <cuda_runtime.h>
#include <math.h>

// Problem constants (fixed shapes)
#define T_ 4
#define B_ 16
#define C_ 256
#define N_ 1024          // H*W = 32*32
#define HD_ 1024         // 4*C
#define HEADS_ 8
#define DH_ 32           // C/HEADS
#define TB_ (T_*B_)      // 64 batched GEMMs

#define S_CN   ((size_t)B_*C_*N_)        // 4,194,304  (per-timestep elems, C channels)
#define S_HN   ((size_t)B_*HD_*N_)       // 16,777,216 (per-timestep elems, HD channels)
#define TCN    ((size_t)T_*S_CN)         // 16,777,216
#define THN    ((size_t)T_*S_HN)         // 67,108,864

// ---------------- scratch (static device globals; no runtime allocation) ----
__device__ float g_q [TCN];
__device__ float g_k [TCN];
__device__ float g_v [TCN];
__device__ float g_a [TCN];
__device__ float g_p [TCN];   // proj pre-act, then becomes x1 = x + attn_out
__device__ float g_y2[TCN];   // fc2 pre-act
__device__ float g_h1[THN];   // fc1 pre-act -> spikes (in place)

// per-layer BN affine params: layers 0=q 1=k 2=v 3=proj 4=fc1 5=fc2
__device__ float g_alpha[6*1024];
__device__ float g_off  [6*1024];
__device__ float g_beta [6*1024];

// ---------------- prep: fold BN (+bias) into per-channel affine -------------
__global__ void prep_kernel(const float* __restrict__ bn_q,
                            const float* __restrict__ bn_k,
                            const float* __restrict__ bn_v,
                            const float* __restrict__ b_proj,
                            const float* __restrict__ bn_proj,
                            const float* __restrict__ b_fc1,
                            const float* __restrict__ bn_fc1,
                            const float* __restrict__ b_fc2,
                            const float* __restrict__ bn_fc2)
{
    int i = threadIdx.x;   // 0..1023
    const float* bns [6] = {bn_q, bn_k, bn_v, bn_proj, bn_fc1, bn_fc2};
    const float* bias[6] = {0,    0,    0,    b_proj,  b_fc1,  b_fc2 };
    int          cn  [6] = {C_,   C_,   C_,   C_,      HD_,    C_    };
    for (int l = 0; l < 6; l++) {
        int Cn = cn[l];
        if (i < Cn) {
            float g  = bns[l][0*Cn + i];
            float be = bns[l][1*Cn + i];
            float m  = bns[l][2*Cn + i];
            float va = bns[l][3*Cn + i];
            float rs = (float)(1.0 / sqrt((double)va + 1e-5));
            g_alpha[l*1024 + i] = g * rs;
            g_off  [l*1024 + i] = (bias[l] ? bias[l][i] : 0.0f) - m;
            g_beta [l*1024 + i] = be;
        }
    }
}

// ---------------- batched GEMM + BN-affine epilogue -------------------------
// Y[tb, o, n] = alpha[o] * ( sum_c W[o,c] * X[tb,c,n] + off[o] ) + beta[o]
// tiles: 128x128x8, 256 threads, 8x8 per thread, prefetch into registers.
template<int Mc, int Kc>
__global__ __launch_bounds__(256)
void gemm_bn(const float* __restrict__ A,      // [Mc, Kc] weights (row-major)
             const float* __restrict__ X,      // [TB, Kc, N_]
             float* __restrict__ Y,            // [TB, Mc, N_]
             const float* __restrict__ alpha,
             const float* __restrict__ off,
             const float* __restrict__ beta)
{
    constexpr int TILE = 128;
    constexpr int BK = 8;
    const int NN = N_;

    int bnx = blockIdx.x;           // n-tile
    int bm  = blockIdx.y;           // m-tile
    int tb  = blockIdx.z;           // batch

    const float* Xb = X + (size_t)tb * Kc * NN;
    float*       Yb = Y + (size_t)tb * Mc * NN;

    __shared__ float As[BK][TILE];
    __shared__ float Bs[BK][TILE];

    int tid = threadIdx.x;
    int tx = tid & 15;              // n direction (16)
    int ty = tid >> 4;              // m direction (16)

    // global load mapping
    int arow = tid >> 1;            // 0..127
    int acol = (tid & 1) * 4;       // 0 or 4
    int brow = tid >> 5;            // 0..7
    int bcol = (tid & 31) * 4;      // 0..124

    const float* Aptr = A + (size_t)(bm*TILE + arow) * Kc + acol;
    const float* Bptr = Xb + (size_t)brow * NN + bnx*TILE + bcol;

    float acc[8][8];
    #pragma unroll
    for (int i = 0; i < 8; i++)
        #pragma unroll
        for (int j = 0; j < 8; j++) acc[i][j] = 0.0f;

    float4 a4 = *(const float4*)(Aptr);
    float4 b4 = *(const float4*)(Bptr);

    for (int k0 = 0; k0 < Kc; k0 += BK) {
        As[acol+0][arow] = a4.x;
        As[acol+1][arow] = a4.y;
        As[acol+2][arow] = a4.z;
        As[acol+3][arow] = a4.w;
        *(float4*)&Bs[brow][bcol] = b4;
        __syncthreads();

        if (k0 + BK < Kc) {
            a4 = *(const float4*)(Aptr + k0 + BK);
            b4 = *(const float4*)(Bptr + (size_t)(k0 + BK) * NN);
        }

        #pragma unroll
        for (int kk = 0; kk < BK; kk++) {
            float af[8], bf[8];
            #pragma unroll
            for (int i = 0; i < 8; i++) af[i] = As[kk][ty*8 + i];
            #pragma unroll
            for (int j = 0; j < 8; j++) bf[j] = Bs[kk][tx*8 + j];
            #pragma unroll
            for (int i = 0; i < 8; i++)
                #pragma unroll
                for (int j = 0; j < 8; j++)
                    acc[i][j] += af[i] * bf[j];
        }
        __syncthreads();
    }

    // epilogue: BN affine
    #pragma unroll
    for (int i = 0; i < 8; i++) {
        int o = bm*TILE + ty*8 + i;
        float al = alpha[o], of = off[o], be = beta[o];
        float* yrow = Yb + (size_t)o * NN + bnx*TILE + tx*8;
        float4 r0, r1;
        r0.x = al*(acc[i][0]+of)+be; r0.y = al*(acc[i][1]+of)+be;
        r0.z = al*(acc[i][2]+of)+be; r0.w = al*(acc[i][3]+of)+be;
        r1.x = al*(acc[i][4]+of)+be; r1.y = al*(acc[i][5]+of)+be;
        r1.z = al*(acc[i][6]+of)+be; r1.w = al*(acc[i][7]+of)+be;
        *(float4*)(yrow)     = r0;
        *(float4*)(yrow + 4) = r1;
    }
}

// ---------------- LIF kernels (scan over T in registers) --------------------
// in place: y <- spikes(lif(y))
__global__ void lif_kernel(float* __restrict__ y, int S, float vth)
{
    int i = blockIdx.x * blockDim.x + threadIdx.x;
    if (i >= S) return;
    float v = 0.0f;
    #pragma unroll
    for (int t = 0; t < T_; t++) {
        size_t idx = (size_t)t * S + i;
        float xx = y[idx];
        v = v + (xx - v) * 0.5f;
        float s = (v >= vth) ? 1.0f : 0.0f;
        y[idx] = s;
        if (s != 0.0f) v = 0.0f;
    }
}

// p <- x + lif_spike(p), vth = 1
__global__ void lif_add_kernel(float* __restrict__ p, const float* __restrict__ x, int S)
{
    int i = blockIdx.x * blockDim.x + threadIdx.x;
    if (i >= S) return;
    float v = 0.0f;
    #pragma unroll
    for (int t = 0; t < T_; t++) {
        size_t idx = (size_t)t * S + i;
        float xx = p[idx];
        v = v + (xx - v) * 0.5f;
        float s = (v >= 1.0f) ? 1.0f : 0.0f;
        p[idx] = x[idx] + s;
        if (s != 0.0f) v = 0.0f;
    }
}

// out <- x1 + lif_spike(y2), vth = 1
__global__ void lif_final_kernel(const float* __restrict__ y2,
                                 const float* __restrict__ x1,
                                 float* __restrict__ out, int S)
{
    int i = blockIdx.x * blockDim.x + threadIdx.x;
    if (i >= S) return;
    float v = 0.0f;
    #pragma unroll
    for (int t = 0; t < T_; t++) {
        size_t idx = (size_t)t * S + i;
        float xx = y2[idx];
        v = v + (xx - v) * 0.5f;
        float s = (v >= 1.0f) ? 1.0f : 0.0f;
        out[idx] = x1[idx] + s;
        if (s != 0.0f) v = 0.0f;
    }
}

// ---------------- linear attention (all-binary: bitpack + popcount) ---------
// one block per (t,b,h): kv[d][e] = popc(k_bits[d] & v_bits[e]);
// a[h*32+e][n] = 0.125 * sum_{d: q[n,d]=1} kv[d][e]    (all integer-exact)
__global__ __launch_bounds__(256)
void attn_kernel(const float* __restrict__ sq,
                 const float* __restrict__ sk,
                 const float* __restrict__ sv,
                 float* __restrict__ a)
{
    int blk = blockIdx.x;           // 0..511
    int h  = blk & 7;
    int tb = blk >> 3;

    const size_t base = ((size_t)tb * C_ + h * DH_) * N_;
    const float* Ks = sk + base;
    const float* Vs = sv + base;
    const float* Qs = sq + base;
    float*       Ao = a  + base;

    __shared__ unsigned kb[DH_][32];
    __shared__ unsigned vb[DH_][32];
    __shared__ float    kv[DH_][DH_ + 1];

    int tid  = threadIdx.x;
    int lane = tid & 31;
    int warp = tid >> 5;            // 8 warps

    // bitpack k,v spikes: row-per-warp, ballot per 32-n chunk
    for (int row = warp; row < 2*DH_; row += 8) {
        const float* src = (row < DH_) ? (Ks + (size_t)row * N_)
                                       : (Vs + (size_t)(row - DH_) * N_);
        unsigned* dst = (row < DH_) ? kb[row] : vb[row - DH_];
        for (int w = 0; w < 32; w++) {
            unsigned m = __ballot_sync(0xffffffffu, src[w*32 + lane] >= 0.5f);
            if (lane == 0) dst[w] = m;
        }
    }
    __syncthreads();

    // kv = K^T V via AND+popcount (exact integer counts)
    for (int e = tid; e < DH_*DH_; e += 256) {
        int dd = e >> 5, ee = e & 31;
        int cnt = 0;
        #pragma unroll
        for (int w = 0; w < 32; w++) cnt += __popc(kb[dd][w] & vb[ee][w]);
        kv[dd][ee] = (float)cnt;
    }
    __syncthreads();

    // a[n, e] = 0.125 * sum_{d: q=1} kv[d][e]
    for (int n = tid; n < N_; n += 256) {
        float acc[DH_];
        #pragma unroll
        for (int e = 0; e < DH_; e++) acc[e] = 0.0f;
        #pragma unroll
        for (int dd = 0; dd < DH_; dd++) {
            bool on = Qs[(size_t)dd * N_ + n] >= 0.5f;
            if (on) {
                #pragma unroll
                for (int e = 0; e < DH_; e++) acc[e] += kv[dd][e];
            }
        }
        #pragma unroll
        for (int e = 0; e < DH_; e++)
            Ao[(size_t)e * N_ + n] = acc[e] * 0.125f;
    }
}

// ---------------- launch ----------------------------------------------------
extern "C" void kernel_launch(void* const* d_in, const int* in_sizes, int n_in,
                              void* d_out, int out_size)
{
    const float* x       = (const float*)d_in[0];
    // d_in[1] = res_attn (unused, zeros)
    const float* wq      = (const float*)d_in[2];
    const float* bn_q    = (const float*)d_in[3];
    const float* wk      = (const float*)d_in[4];
    const float* bn_k    = (const float*)d_in[5];
    const float* wv      = (const float*)d_in[6];
    const float* bn_v    = (const float*)d_in[7];
    const float* w_proj  = (const float*)d_in[8];
    const float* b_proj  = (const float*)d_in[9];
    const float* bn_proj = (const float*)d_in[10];
    const float* w_fc1   = (const float*)d_in[11];
    const float* b_fc1   = (const float*)d_in[12];
    const float* bn_fc1  = (const float*)d_in[13];
    const float* w_fc2   = (const float*)d_in[14];
    const float* b_fc2   = (const float*)d_in[15];
    const float* bn_fc2  = (const float*)d_in[16];
    float* out = (float*)d_out;

    float *q, *k, *v, *a, *p, *y2, *h1, *al, *of, *be;
    cudaGetSymbolAddress((void**)&q,  g_q);
    cudaGetSymbolAddress((void**)&k,  g_k);
    cudaGetSymbolAddress((void**)&v,  g_v);
    cudaGetSymbolAddress((void**)&a,  g_a);
    cudaGetSymbolAddress((void**)&p,  g_p);
    cudaGetSymbolAddress((void**)&y2, g_y2);
    cudaGetSymbolAddress((void**)&h1, g_h1);
    cudaGetSymbolAddress((void**)&al, g_alpha);
    cudaGetSymbolAddress((void**)&of, g_off);
    cudaGetSymbolAddress((void**)&be, g_beta);

    prep_kernel<<<1, 1024>>>(bn_q, bn_k, bn_v, b_proj, bn_proj,
                             b_fc1, bn_fc1, b_fc2, bn_fc2);

    const int SC = (int)S_CN;   // 4,194,304
    const int SH = (int)S_HN;   // 16,777,216
    dim3 blk256(256);

    // q,k,v conv1x1 + BN
    gemm_bn<C_, C_><<<dim3(8, 2, TB_), blk256>>>(wq, x, q, al + 0*1024, of + 0*1024, be + 0*1024);
    gemm_bn<C_, C_><<<dim3(8, 2, TB_), blk256>>>(wk, x, k, al + 1*1024, of + 1*1024, be + 1*1024);
    gemm_bn<C_, C_><<<dim3(8, 2, TB_), blk256>>>(wv, x, v, al + 2*1024, of + 2*1024, be + 2*1024);

    lif_kernel<<<SC/256, blk256>>>(q, SC, 1.0f);
    lif_kernel<<<SC/256, blk256>>>(k, SC, 1.0f);
    lif_kernel<<<SC/256, blk256>>>(v, SC, 1.0f);

    // linear attention (exact integer path), then attn_lif (vth=0.5)
    attn_kernel<<<TB_*HEADS_, blk256>>>(q, k, v, a);
    lif_kernel<<<SC/256, blk256>>>(a, SC, 0.5f);

    // proj + BN, then x1 = x + spike  (x1 stored in p)
    gemm_bn<C_, C_><<<dim3(8, 2, TB_), blk256>>>(w_proj, a, p, al + 3*1024, of + 3*1024, be + 3*1024);
    lif_add_kernel<<<SC/256, blk256>>>(p, x, SC);

    // fc1 + BN + LIF
    gemm_bn<HD_, C_><<<dim3(8, 8, TB_), blk256>>>(w_fc1, p, h1, al + 4*1024, of + 4*1024, be + 4*1024);
    lif_kernel<<<SH/256, blk256>>>(h1, SH, 1.0f);

    // fc2 + BN, then out = x1 + spike
    gemm_bn<C_, HD_><<<dim3(8, 2, TB_), blk256>>>(w_fc2, h1, y2, al + 5*1024, of + 5*1024, be + 5*1024);
    lif_final_kernel<<<SC/256, blk256>>>(y2, p, out, SC);
}

// round 6
// speedup vs baseline: 1.2467x; 1.2467x over previous
#include <cuda_runtime.h>
#include <cuda_bf16.h>
#include <math.h>
#include <stdint.h>

// ---------------- shapes -----------------------------------------------------
#define T_ 4
#define B_ 16
#define C_ 256
#define N_ 1024
#define HD_ 1024
#define HEADS_ 8
#define TB_ (T_*B_)

#define S_C   ((size_t)B_*N_*C_)        // 4,194,304
#define S_QKV ((size_t)B_*N_*768)       // 12,582,912
#define S_H   ((size_t)B_*N_*HD_)       // 16,777,216
#define TCN   ((size_t)T_*S_C)
#define TQKV  ((size_t)T_*S_QKV)
#define THN   ((size_t)T_*S_H)

// real-path weights: rows 0..767 = wq|wk|wv, rows 768..1791 = w_fc1; K=256
#define WR_ROWS 1792
#define WR_SZ   (WR_ROWS*256)           // 458752
// affine concat offsets (channels)
#define AOFF_QKV  0
#define AOFF_P    768
#define AOFF_F1   1024
#define AOFF_F2   2048
#define ATOT      2304

// ---------------- device scratch ---------------------------------------------
__device__ __nv_bfloat16 g_wr  [3][WR_SZ];     // bf16 3-split (qkv + fc1)
__device__ __nv_bfloat16 g_wpb [3][65536];     // bf16 3-split proj
__device__ __nv_bfloat16 g_wf2b[3][262144];    // bf16 3-split fc2
__device__ float g_alpha[ATOT], g_off[ATOT], g_beta[ATOT];

__device__ float         g_xt  [TCN];          // x [tb][n][c] fp32
__device__ __nv_bfloat16 g_xsp [3][TCN];       // x bf16 3-split
__device__ float         g_qkv [TQKV];         // qkv preact -> spikes
__device__ float         g_a   [TCN];          // attn values
__device__ __nv_bfloat16 g_ab  [TCN];          // attn spikes bf16
__device__ float         g_p   [TCN];          // proj preact
__device__ float         g_x1  [TCN];          // x + attn spikes
__device__ __nv_bfloat16 g_ps  [3][TCN];       // x1 bf16 3-split
__device__ float         g_h1  [THN];          // fc1 preact
__device__ __nv_bfloat16 g_h1b [THN];          // fc1 spikes bf16
__device__ float         g_y2  [TCN];          // fc2 preact

// ---------------- helpers ----------------------------------------------------
__device__ __forceinline__ uint32_t smem_u32(const void* p) {
    uint32_t a;
    asm("{ .reg .u64 t; cvta.to.shared.u64 t, %1; cvt.u32.u64 %0, t; }" : "=r"(a) : "l"(p));
    return a;
}
#define CP_ASYNC16(dst, src) \
    asm volatile("cp.async.cg.shared.global [%0], [%1], 16;\n" :: "r"(dst), "l"(src))
#define CP_COMMIT() asm volatile("cp.async.commit_group;\n" ::: "memory")
#define CP_WAIT(n)  asm volatile("cp.async.wait_group %0;\n" :: "n"(n) : "memory")

__device__ __forceinline__ void split3(float x, __nv_bfloat16& a, __nv_bfloat16& b,
                                       __nv_bfloat16& c) {
    a = __float2bfloat16(x); float r = x - __bfloat162float(a);
    b = __float2bfloat16(r); r -= __bfloat162float(b);
    c = __float2bfloat16(r);
}

__device__ __forceinline__ void mma_bf16(float* c, const uint32_t* a, const uint32_t* b) {
    asm volatile("mma.sync.aligned.m16n8k16.row.col.f32.bf16.bf16.f32 "
        "{%0,%1,%2,%3}, {%4,%5,%6,%7}, {%8,%9}, {%0,%1,%2,%3};"
        : "+f"(c[0]), "+f"(c[1]), "+f"(c[2]), "+f"(c[3])
        : "r"(a[0]), "r"(a[1]), "r"(a[2]), "r"(a[3]), "r"(b[0]), "r"(b[1]));
}

// ---------------- prep kernels -----------------------------------------------
__global__ void prep_aff(const float* __restrict__ bn_q, const float* __restrict__ bn_k,
                         const float* __restrict__ bn_v, const float* __restrict__ b_proj,
                         const float* __restrict__ bn_proj, const float* __restrict__ b_fc1,
                         const float* __restrict__ bn_fc1, const float* __restrict__ b_fc2,
                         const float* __restrict__ bn_fc2)
{
    for (int i = threadIdx.x; i < ATOT; i += blockDim.x) {
        const float* bn; const float* bias = 0; int Cn, ch;
        if (i < 256)       { bn = bn_q;    Cn = 256;  ch = i; }
        else if (i < 512)  { bn = bn_k;    Cn = 256;  ch = i - 256; }
        else if (i < 768)  { bn = bn_v;    Cn = 256;  ch = i - 512; }
        else if (i < 1024) { bn = bn_proj; Cn = 256;  ch = i - 768;  bias = b_proj; }
        else if (i < 2048) { bn = bn_fc1;  Cn = 1024; ch = i - 1024; bias = b_fc1; }
        else               { bn = bn_fc2;  Cn = 256;  ch = i - 2048; bias = b_fc2; }
        float g = bn[0*Cn+ch], be = bn[1*Cn+ch], m = bn[2*Cn+ch], va = bn[3*Cn+ch];
        float rs = (float)(1.0 / sqrt((double)va + 1e-5));
        g_alpha[i] = g * rs;
        g_off[i]   = (bias ? bias[ch] : 0.0f) - m;
        g_beta[i]  = be;
    }
}

__global__ void prep_w_real(const float* __restrict__ wq, const float* __restrict__ wk,
                            const float* __restrict__ wv, const float* __restrict__ wf1)
{
    int i = blockIdx.x * 256 + threadIdx.x;
    if (i >= WR_SZ) return;
    int row = i >> 8, k = i & 255;
    float w;
    if (row < 256)       w = wq[row*256 + k];
    else if (row < 512)  w = wk[(row-256)*256 + k];
    else if (row < 768)  w = wv[(row-512)*256 + k];
    else                 w = wf1[(row-768)*256 + k];
    split3(w, g_wr[0][i], g_wr[1][i], g_wr[2][i]);
}

__global__ void prep_w_bin(const float* __restrict__ wp, const float* __restrict__ wf2)
{
    int i = blockIdx.x * 256 + threadIdx.x;
    if (i >= 65536 + 262144) return;
    if (i < 65536) split3(wp[i], g_wpb[0][i], g_wpb[1][i], g_wpb[2][i]);
    else { int j = i - 65536; split3(wf2[j], g_wf2b[0][j], g_wf2b[1][j], g_wf2b[2][j]); }
}

// x [tb][c][n] -> g_xt [tb][n][c] fp32 + bf16 3-split
__global__ void transpose_split(const float* __restrict__ x)
{
    __shared__ float tile[32][33];
    int c0 = blockIdx.x * 32, n0 = blockIdx.y * 32, tb = blockIdx.z;
    int tx = threadIdx.x & 31, ty = threadIdx.x >> 5;
    const float* xb = x + (size_t)tb * C_ * N_;
    #pragma unroll
    for (int j = 0; j < 4; j++)
        tile[ty + 8*j][tx] = xb[(size_t)(c0 + ty + 8*j) * N_ + n0 + tx];
    __syncthreads();
    #pragma unroll
    for (int j = 0; j < 4; j++) {
        int n = n0 + ty + 8*j, c = c0 + tx;
        float v = tile[tx][ty + 8*j];
        size_t idx = ((size_t)tb * N_ + n) * C_ + c;
        g_xt[idx] = v;
        split3(v, g_xsp[0][idx], g_xsp[1][idx], g_xsp[2][idx]);
    }
}

// ---------------- mma.sync split-GEMM ----------------------------------------
// Y[tb][n][m] = alpha[m]*( sum_k W[m,k]*Act[tb,n,k] + off[m] ) + beta[m]
// Block: 128n x 128m, 8 warps (2n x 4m), warp tile 64n x 32m.
// Term order: SMALL correction terms FIRST, main term (w0*x0) LAST, so the
// accumulator stays tiny while corrections land (negligible rounding) and the
// main chain rounds exactly like a plain fp32 accumulation (matches the
// passing fp32 kernel's error class).
template<int KTOT, int NT>
__global__ __launch_bounds__(256)
void gemm_mma(const __nv_bfloat16* __restrict__ Act, size_t actStride,
              const __nv_bfloat16* __restrict__ Wt, size_t wStride,
              float* __restrict__ Y, int Mtot,
              const float* __restrict__ alpha, const float* __restrict__ offv,
              const float* __restrict__ beta)
{
    constexpr int KC   = KTOT / 32;
    constexpr int NSEG = NT * KC;
    constexpr int PITCH  = 80;
    constexpr int TILEB  = 128 * PITCH;     // 10240
    constexpr int STAGEB = 2 * TILEB;       // 20480

    extern __shared__ char smem[];
    const uint32_t sb = smem_u32(smem);
    const int tid  = threadIdx.x;
    const int lane = tid & 31, warp = tid >> 5;
    const int wn = warp & 1, wm = warp >> 1;
    const int n0 = blockIdx.x * 128, m0 = blockIdx.y * 128;
    const int tbz = blockIdx.z;

    // corrections first, main (w0 x0) last
    const int TA6[6] = {0,1,1,0,2,0};
    const int TB6[6] = {1,0,1,2,0,0};
    const int TW3[3] = {1,2,0};

    const int r_ = tid >> 2, c_ = tid & 3;

    auto load = [&](int seg, int st) {
        if (seg < NSEG) {
            int term = seg / KC, kc = seg - term * KC;
            int wa = (NT == 6) ? TA6[term] : TW3[term];
            int xb = (NT == 6) ? TB6[term] : 0;
            const __nv_bfloat16* ap = Act + (size_t)xb * actStride
                          + ((size_t)tbz * N_ + n0) * KTOT + kc * 32;
            const __nv_bfloat16* wp = Wt + (size_t)wa * wStride + (size_t)m0 * KTOT + kc * 32;
            uint32_t ab = sb + st * STAGEB, bb = ab + TILEB;
            #pragma unroll
            for (int j = 0; j < 2; j++) {
                int r = r_ + j * 64;
                CP_ASYNC16(ab + r * PITCH + c_ * 16, ap + (size_t)r * KTOT + c_ * 8);
                CP_ASYNC16(bb + r * PITCH + c_ * 16, wp + (size_t)r * KTOT + c_ * 8);
            }
        }
        CP_COMMIT();
    };

    float acc[4][4][4];
    #pragma unroll
    for (int i = 0; i < 4; i++)
        #pragma unroll
        for (int j = 0; j < 4; j++)
            #pragma unroll
            for (int v = 0; v < 4; v++) acc[i][j][v] = 0.0f;

    load(0, 0);
    load(1, 1);

    for (int seg = 0; seg < NSEG; ++seg) {
        CP_WAIT(1);
        __syncthreads();
        load(seg + 2, (seg + 2) % 3);

        uint32_t ab = sb + (seg % 3) * STAGEB, bb = ab + TILEB;
        #pragma unroll
        for (int ki = 0; ki < 2; ki++) {
            uint32_t a[4][4];
            #pragma unroll
            for (int ni = 0; ni < 4; ni++) {
                int row = wn * 64 + ni * 16 + (lane & 15);
                int cc  = ki * 2 + (lane >> 4);
                uint32_t ad = ab + row * PITCH + cc * 16;
                asm volatile("ldmatrix.sync.aligned.m8n8.x4.shared.b16 {%0,%1,%2,%3}, [%4];"
                    : "=r"(a[ni][0]), "=r"(a[ni][1]), "=r"(a[ni][2]), "=r"(a[ni][3])
                    : "r"(ad));
            }
            uint32_t b[4][2];
            #pragma unroll
            for (int mi2 = 0; mi2 < 2; mi2++) {
                int row = wm * 32 + mi2 * 16 + (lane & 7) + ((lane >> 4) << 3);
                int cc  = ki * 2 + ((lane >> 3) & 1);
                uint32_t bd = bb + row * PITCH + cc * 16;
                uint32_t r0, r1, r2, r3;
                asm volatile("ldmatrix.sync.aligned.m8n8.x4.shared.b16 {%0,%1,%2,%3}, [%4];"
                    : "=r"(r0), "=r"(r1), "=r"(r2), "=r"(r3) : "r"(bd));
                b[mi2*2+0][0] = r0; b[mi2*2+0][1] = r1;
                b[mi2*2+1][0] = r2; b[mi2*2+1][1] = r3;
            }
            #pragma unroll
            for (int ni = 0; ni < 4; ni++)
                #pragma unroll
                for (int mi = 0; mi < 4; mi++)
                    mma_bf16(acc[ni][mi], a[ni], b[mi]);
        }
    }

    // epilogue: BN affine + store [n][m] (float2, 32B-sector coalesced)
    const int group = lane >> 2, tig = lane & 3;
    #pragma unroll
    for (int mi = 0; mi < 4; mi++) {
        int m = m0 + wm * 32 + mi * 8 + tig * 2;
        float2 al = *(const float2*)&alpha[m];
        float2 of = *(const float2*)&offv[m];
        float2 be = *(const float2*)&beta[m];
        #pragma unroll
        for (int ni = 0; ni < 4; ni++)
            #pragma unroll
            for (int v = 0; v < 2; v++) {
                int n = n0 + wn * 64 + ni * 16 + group + v * 8;
                float2 val;
                val.x = al.x * (acc[ni][mi][v*2+0] + of.x) + be.x;
                val.y = al.y * (acc[ni][mi][v*2+1] + of.y) + be.y;
                *(float2*)&Y[((size_t)tbz * N_ + n) * Mtot + m] = val;
            }
    }
}

// ---------------- LIF kernels ------------------------------------------------
__global__ void lif_inplace(float* __restrict__ y, size_t S, float vth)
{
    size_t i = (size_t)blockIdx.x * blockDim.x + threadIdx.x;
    if (i >= S) return;
    float v = 0.0f;
    #pragma unroll
    for (int t = 0; t < T_; t++) {
        size_t idx = (size_t)t * S + i;
        float xx = y[idx];
        v = v + (xx - v) * 0.5f;
        float s = (v >= vth) ? 1.0f : 0.0f;
        y[idx] = s;
        if (s != 0.0f) v = 0.0f;
    }
}
__global__ void lif_to_bf16(const float* __restrict__ y, __nv_bfloat16* __restrict__ o,
                            size_t S, float vth)
{
    size_t i = (size_t)blockIdx.x * blockDim.x + threadIdx.x;
    if (i >= S) return;
    float v = 0.0f;
    #pragma unroll
    for (int t = 0; t < T_; t++) {
        size_t idx = (size_t)t * S + i;
        float xx = y[idx];
        v = v + (xx - v) * 0.5f;
        float s = (v >= vth) ? 1.0f : 0.0f;
        o[idx] = __float2bfloat16(s);
        if (s != 0.0f) v = 0.0f;
    }
}
// x1 = xt + spike(p); write x1 and its bf16 3-split
__global__ void lif_add_split(const float* __restrict__ p, size_t S)
{
    size_t i = (size_t)blockIdx.x * blockDim.x + threadIdx.x;
    if (i >= S) return;
    float v = 0.0f;
    #pragma unroll
    for (int t = 0; t < T_; t++) {
        size_t idx = (size_t)t * S + i;
        float xx = p[idx];
        v = v + (xx - v) * 0.5f;
        float s = (v >= 1.0f) ? 1.0f : 0.0f;
        float x1 = g_xt[idx] + s;
        g_x1[idx] = x1;
        split3(x1, g_ps[0][idx], g_ps[1][idx], g_ps[2][idx]);
        if (s != 0.0f) v = 0.0f;
    }
}
// out[t,b,c,n] = x1 + spike(y2); internal buffers are [tb][n][c]
__global__ void lif_final(float* __restrict__ out, size_t S)
{
    size_t i = (size_t)blockIdx.x * blockDim.x + threadIdx.x;
    if (i >= S) return;
    int b = (int)(i / ((size_t)N_ * C_));
    int r = (int)(i % ((size_t)N_ * C_));
    int n = r >> 8, c = r & 255;
    float v = 0.0f;
    #pragma unroll
    for (int t = 0; t < T_; t++) {
        size_t idx = (size_t)t * S + i;
        float xx = g_y2[idx];
        v = v + (xx - v) * 0.5f;
        float s = (v >= 1.0f) ? 1.0f : 0.0f;
        out[(((size_t)t * B_ + b) * C_ + c) * N_ + n] = g_x1[idx] + s;
        if (s != 0.0f) v = 0.0f;
    }
}

// ---------------- attention (exact integer-valued fp32) ----------------------
__global__ __launch_bounds__(256) void attn_kernel()
{
    int h  = blockIdx.x & 7;
    int tb = blockIdx.x >> 3;
    const float* base = g_qkv + (size_t)tb * N_ * 768;

    __shared__ float ks[128][33];
    __shared__ float vs[128][36];
    __shared__ float kvs[32][33];

    int tid = threadIdx.x;
    int d  = tid >> 3;
    int e4 = (tid & 7) * 4;
    float acc[4] = {0.f, 0.f, 0.f, 0.f};

    for (int n0 = 0; n0 < N_; n0 += 128) {
        for (int i = tid; i < 128 * 32; i += 256) {
            int nl = i >> 5, dd = i & 31;
            const float* row = base + (size_t)(n0 + nl) * 768 + h * 32;
            ks[nl][dd] = row[256 + dd];
            vs[nl][dd] = row[512 + dd];
        }
        __syncthreads();
        for (int n = 0; n < 128; n++) {
            float kd = ks[n][d];
            float4 vv = *(const float4*)&vs[n][e4];
            acc[0] += kd * vv.x; acc[1] += kd * vv.y;
            acc[2] += kd * vv.z; acc[3] += kd * vv.w;
        }
        __syncthreads();
    }
    kvs[d][e4+0] = acc[0]; kvs[d][e4+1] = acc[1];
    kvs[d][e4+2] = acc[2]; kvs[d][e4+3] = acc[3];
    __syncthreads();

    for (int n = tid; n < N_; n += 256) {
        const float* qrow = base + (size_t)n * 768 + h * 32;
        float a[32];
        #pragma unroll
        for (int e = 0; e < 32; e++) a[e] = 0.0f;
        #pragma unroll
        for (int dd = 0; dd < 32; dd++) {
            if (qrow[dd] != 0.0f) {
                #pragma unroll
                for (int e = 0; e < 32; e++) a[e] += kvs[dd][e];
            }
        }
        float* ao = g_a + ((size_t)tb * N_ + n) * C_ + h * 32;
        #pragma unroll
        for (int e = 0; e < 32; e += 4) {
            float4 w;
            w.x = a[e]*0.125f; w.y = a[e+1]*0.125f;
            w.z = a[e+2]*0.125f; w.w = a[e+3]*0.125f;
            *(float4*)(ao + e) = w;
        }
    }
}

// ---------------- launch -----------------------------------------------------
extern "C" void kernel_launch(void* const* d_in, const int* in_sizes, int n_in,
                              void* d_out, int out_size)
{
    const float* x       = (const float*)d_in[0];
    const float* wq      = (const float*)d_in[2];
    const float* bn_q    = (const float*)d_in[3];
    const float* wk      = (const float*)d_in[4];
    const float* bn_k    = (const float*)d_in[5];
    const float* wv      = (const float*)d_in[6];
    const float* bn_v    = (const float*)d_in[7];
    const float* w_proj  = (const float*)d_in[8];
    const float* b_proj  = (const float*)d_in[9];
    const float* bn_proj = (const float*)d_in[10];
    const float* w_fc1   = (const float*)d_in[11];
    const float* b_fc1   = (const float*)d_in[12];
    const float* bn_fc1  = (const float*)d_in[13];
    const float* w_fc2   = (const float*)d_in[14];
    const float* b_fc2   = (const float*)d_in[15];
    const float* bn_fc2  = (const float*)d_in[16];
    float* out = (float*)d_out;

    __nv_bfloat16 *wr, *xsp, *ps, *wpb, *wf2b, *ab, *h1b;
    float *qkv, *a, *p, *h1, *y2, *al, *of, *be;
    cudaGetSymbolAddress((void**)&wr,   g_wr);
    cudaGetSymbolAddress((void**)&wpb,  g_wpb);
    cudaGetSymbolAddress((void**)&wf2b, g_wf2b);
    cudaGetSymbolAddress((void**)&xsp,  g_xsp);
    cudaGetSymbolAddress((void**)&ps,   g_ps);
    cudaGetSymbolAddress((void**)&ab,   g_ab);
    cudaGetSymbolAddress((void**)&h1b,  g_h1b);
    cudaGetSymbolAddress((void**)&qkv,  g_qkv);
    cudaGetSymbolAddress((void**)&a,    g_a);
    cudaGetSymbolAddress((void**)&p,    g_p);
    cudaGetSymbolAddress((void**)&h1,   g_h1);
    cudaGetSymbolAddress((void**)&y2,   g_y2);
    cudaGetSymbolAddress((void**)&al,   g_alpha);
    cudaGetSymbolAddress((void**)&of,   g_off);
    cudaGetSymbolAddress((void**)&be,   g_beta);

    const int SMEM = 3 * 20480;   // 61440
    cudaFuncSetAttribute(gemm_mma<256,6>,
                         cudaFuncAttributeMaxDynamicSharedMemorySize, SMEM);
    cudaFuncSetAttribute(gemm_mma<256,3>,
                         cudaFuncAttributeMaxDynamicSharedMemorySize, SMEM);
    cudaFuncSetAttribute(gemm_mma<1024,3>,
                         cudaFuncAttributeMaxDynamicSharedMemorySize, SMEM);

    prep_aff<<<1, 256>>>(bn_q, bn_k, bn_v, b_proj, bn_proj, b_fc1, bn_fc1, b_fc2, bn_fc2);
    prep_w_real<<<(WR_SZ + 255)/256, 256>>>(wq, wk, wv, w_fc1);
    prep_w_bin<<<(65536 + 262144 + 255)/256, 256>>>(w_proj, w_fc2);
    transpose_split<<<dim3(8, 32, TB_), 256>>>(x);

    // qkv: M=768, bf16 6-term
    gemm_mma<256,6><<<dim3(8, 6, TB_), 256, SMEM>>>(
        xsp, TCN, wr, WR_SZ, qkv, 768, al + AOFF_QKV, of + AOFF_QKV, be + AOFF_QKV);
    lif_inplace<<<(int)(S_QKV/256), 256>>>(qkv, S_QKV, 1.0f);

    attn_kernel<<<TB_ * HEADS_, 256>>>();
    lif_to_bf16<<<(int)(S_C/256), 256>>>(a, ab, S_C, 0.5f);

    // proj: M=256, bf16 3-term (binary input)
    gemm_mma<256,3><<<dim3(8, 2, TB_), 256, SMEM>>>(
        ab, 0, wpb, 65536, p, 256, al + AOFF_P, of + AOFF_P, be + AOFF_P);
    lif_add_split<<<(int)(S_C/256), 256>>>(p, S_C);

    // fc1: M=1024, bf16 6-term (real input), weights at rows 768..1791
    gemm_mma<256,6><<<dim3(8, 8, TB_), 256, SMEM>>>(
        ps, TCN, wr + 768*256, WR_SZ, h1, 1024, al + AOFF_F1, of + AOFF_F1, be + AOFF_F1);
    lif_to_bf16<<<(int)(S_H/256), 256>>>(h1, h1b, S_H, 1.0f);

    // fc2: M=256, K=1024, bf16 3-term (binary input)
    gemm_mma<1024,3><<<dim3(8, 2, TB_), 256, SMEM>>>(
        h1b, 0, wf2b, 262144, y2, 256, al + AOFF_F2, of + AOFF_F2, be + AOFF_F2);
    lif_final<<<(int)(S_C/256), 256>>>(out, S_C);
}

// round 7
// speedup vs baseline: 1.8077x; 1.4500x over previous
#include <cuda_runtime.h>
#include <cuda_fp16.h>
#include <math.h>
#include <stdint.h>

// ---------------- shapes -----------------------------------------------------
#define T_ 4
#define B_ 16
#define C_ 256
#define N_ 1024
#define HD_ 1024
#define HEADS_ 8
#define TB_ (T_*B_)

#define S_C   ((size_t)B_*N_*C_)        // 4,194,304
#define S_QKV ((size_t)B_*N_*768)       // 12,582,912
#define S_H   ((size_t)B_*N_*HD_)       // 16,777,216
#define TCN   ((size_t)T_*S_C)
#define TQKV  ((size_t)T_*S_QKV)
#define THN   ((size_t)T_*S_H)

// real-path weights: rows 0..767 = wq|wk|wv, rows 768..1791 = w_fc1; K=256
#define WR_ROWS 1792
#define WR_SZ   (WR_ROWS*256)           // 458752
// affine concat offsets (channels)
#define AOFF_QKV  0
#define AOFF_P    768
#define AOFF_F1   1024
#define AOFF_F2   2048
#define ATOT      2304

// ---------------- device scratch ---------------------------------------------
__device__ __half g_wr  [2][WR_SZ];     // fp16 2-split (qkv + fc1 weights)
__device__ __half g_wpb [2][65536];     // fp16 2-split proj weights
__device__ __half g_wf2b[2][262144];    // fp16 2-split fc2 weights
__device__ float g_alpha[ATOT], g_off[ATOT], g_beta[ATOT];

__device__ float  g_xt  [TCN];          // x [tb][n][c] fp32
__device__ __half g_xsp [2][TCN];       // x fp16 2-split
__device__ float  g_qkv [TQKV];         // qkv preact -> spikes
__device__ float  g_a   [TCN];          // attn values
__device__ __half g_ab  [TCN];          // attn spikes fp16
__device__ float  g_p   [TCN];          // proj preact
__device__ float  g_x1  [TCN];          // x + attn spikes
__device__ __half g_ps  [2][TCN];       // x1 fp16 2-split
__device__ float  g_h1  [THN];          // fc1 preact
__device__ __half g_h1b [THN];          // fc1 spikes fp16
__device__ float  g_y2  [TCN];          // fc2 preact

// ---------------- helpers ----------------------------------------------------
__device__ __forceinline__ uint32_t smem_u32(const void* p) {
    uint32_t a;
    asm("{ .reg .u64 t; cvta.to.shared.u64 t, %1; cvt.u32.u64 %0, t; }" : "=r"(a) : "l"(p));
    return a;
}
#define CP_ASYNC16(dst, src) \
    asm volatile("cp.async.cg.shared.global [%0], [%1], 16;\n" :: "r"(dst), "l"(src))
#define CP_COMMIT() asm volatile("cp.async.commit_group;\n" ::: "memory")
#define CP_WAIT(n)  asm volatile("cp.async.wait_group %0;\n" :: "n"(n) : "memory")

__device__ __forceinline__ void split2h(float x, __half& a, __half& b) {
    a = __float2half_rn(x); float r = x - __half2float(a);
    b = __float2half_rn(r);
}

__device__ __forceinline__ void mma_f16(float* c, const uint32_t* a, const uint32_t* b) {
    asm volatile("mma.sync.aligned.m16n8k16.row.col.f32.f16.f16.f32 "
        "{%0,%1,%2,%3}, {%4,%5,%6,%7}, {%8,%9}, {%0,%1,%2,%3};"
        : "+f"(c[0]), "+f"(c[1]), "+f"(c[2]), "+f"(c[3])
        : "r"(a[0]), "r"(a[1]), "r"(a[2]), "r"(a[3]), "r"(b[0]), "r"(b[1]));
}

// ---------------- prep kernels -----------------------------------------------
__global__ void prep_aff(const float* __restrict__ bn_q, const float* __restrict__ bn_k,
                         const float* __restrict__ bn_v, const float* __restrict__ b_proj,
                         const float* __restrict__ bn_proj, const float* __restrict__ b_fc1,
                         const float* __restrict__ bn_fc1, const float* __restrict__ b_fc2,
                         const float* __restrict__ bn_fc2)
{
    for (int i = threadIdx.x; i < ATOT; i += blockDim.x) {
        const float* bn; const float* bias = 0; int Cn, ch;
        if (i < 256)       { bn = bn_q;    Cn = 256;  ch = i; }
        else if (i < 512)  { bn = bn_k;    Cn = 256;  ch = i - 256; }
        else if (i < 768)  { bn = bn_v;    Cn = 256;  ch = i - 512; }
        else if (i < 1024) { bn = bn_proj; Cn = 256;  ch = i - 768;  bias = b_proj; }
        else if (i < 2048) { bn = bn_fc1;  Cn = 1024; ch = i - 1024; bias = b_fc1; }
        else               { bn = bn_fc2;  Cn = 256;  ch = i - 2048; bias = b_fc2; }
        float g = bn[0*Cn+ch], be = bn[1*Cn+ch], m = bn[2*Cn+ch], va = bn[3*Cn+ch];
        float rs = (float)(1.0 / sqrt((double)va + 1e-5));
        g_alpha[i] = g * rs;
        g_off[i]   = (bias ? bias[ch] : 0.0f) - m;
        g_beta[i]  = be;
    }
}

__global__ void prep_w_real(const float* __restrict__ wq, const float* __restrict__ wk,
                            const float* __restrict__ wv, const float* __restrict__ wf1)
{
    int i = blockIdx.x * 256 + threadIdx.x;
    if (i >= WR_SZ) return;
    int row = i >> 8, k = i & 255;
    float w;
    if (row < 256)       w = wq[row*256 + k];
    else if (row < 512)  w = wk[(row-256)*256 + k];
    else if (row < 768)  w = wv[(row-512)*256 + k];
    else                 w = wf1[(row-768)*256 + k];
    split2h(w, g_wr[0][i], g_wr[1][i]);
}

__global__ void prep_w_bin(const float* __restrict__ wp, const float* __restrict__ wf2)
{
    int i = blockIdx.x * 256 + threadIdx.x;
    if (i >= 65536 + 262144) return;
    if (i < 65536) split2h(wp[i], g_wpb[0][i], g_wpb[1][i]);
    else { int j = i - 65536; split2h(wf2[j], g_wf2b[0][j], g_wf2b[1][j]); }
}

// x [tb][c][n] -> g_xt [tb][n][c] fp32 + fp16 2-split
__global__ void transpose_split(const float* __restrict__ x)
{
    __shared__ float tile[32][33];
    int c0 = blockIdx.x * 32, n0 = blockIdx.y * 32, tb = blockIdx.z;
    int tx = threadIdx.x & 31, ty = threadIdx.x >> 5;
    const float* xb = x + (size_t)tb * C_ * N_;
    #pragma unroll
    for (int j = 0; j < 4; j++)
        tile[ty + 8*j][tx] = xb[(size_t)(c0 + ty + 8*j) * N_ + n0 + tx];
    __syncthreads();
    #pragma unroll
    for (int j = 0; j < 4; j++) {
        int n = n0 + ty + 8*j, c = c0 + tx;
        float v = tile[tx][ty + 8*j];
        size_t idx = ((size_t)tb * N_ + n) * C_ + c;
        g_xt[idx] = v;
        split2h(v, g_xsp[0][idx], g_xsp[1][idx]);
    }
}

// ---------------- mma.sync fp16 split-GEMM ------------------------------------
// Y[tb][n][m] = alpha[m]*( sum_k W[m,k]*Act[tb,n,k] + off[m] ) + beta[m]
// Block: 128n x 128m, 8 warps (2n x 4m), warp tile 64n x 32m.
// fp16 2-split both operands. Terms ordered corrections-first, main (w0*x0)
// last, single fp32 accumulator (proven safe ordering from R6).
// NT=3 (real input): (w1,x0),(w0,x1),(w0,x0). NT=2 (binary): (w1,s),(w0,s).
template<int KTOT, int NT>
__global__ __launch_bounds__(256)
void gemm_mma(const __half* __restrict__ Act, size_t actStride,
              const __half* __restrict__ Wt, size_t wStride,
              float* __restrict__ Y, int Mtot,
              const float* __restrict__ alpha, const float* __restrict__ offv,
              const float* __restrict__ beta)
{
    constexpr int KC   = KTOT / 32;
    constexpr int NSEG = NT * KC;
    constexpr int PITCH  = 80;
    constexpr int TILEB  = 128 * PITCH;     // 10240
    constexpr int STAGEB = 2 * TILEB;       // 20480

    extern __shared__ char smem[];
    const uint32_t sb = smem_u32(smem);
    const int tid  = threadIdx.x;
    const int lane = tid & 31, warp = tid >> 5;
    const int wn = warp & 1, wm = warp >> 1;
    const int n0 = blockIdx.x * 128, m0 = blockIdx.y * 128;
    const int tbz = blockIdx.z;

    // weight-plane / act-plane index per term (corrections first, main last)
    const int WA3[3] = {1,0,0};
    const int XB3[3] = {0,1,0};
    const int WA2[2] = {1,0};
    const int XB2[2] = {0,0};

    const int r_ = tid >> 2, c_ = tid & 3;

    auto load = [&](int seg, int st) {
        if (seg < NSEG) {
            int term = seg / KC, kc = seg - term * KC;
            int wa = (NT == 3) ? WA3[term] : WA2[term];
            int xb = (NT == 3) ? XB3[term] : XB2[term];
            const __half* ap = Act + (size_t)xb * actStride
                          + ((size_t)tbz * N_ + n0) * KTOT + kc * 32;
            const __half* wp = Wt + (size_t)wa * wStride + (size_t)m0 * KTOT + kc * 32;
            uint32_t ab = sb + st * STAGEB, bb = ab + TILEB;
            #pragma unroll
            for (int j = 0; j < 2; j++) {
                int r = r_ + j * 64;
                CP_ASYNC16(ab + r * PITCH + c_ * 16, ap + (size_t)r * KTOT + c_ * 8);
                CP_ASYNC16(bb + r * PITCH + c_ * 16, wp + (size_t)r * KTOT + c_ * 8);
            }
        }
        CP_COMMIT();
    };

    float acc[4][4][4];
    #pragma unroll
    for (int i = 0; i < 4; i++)
        #pragma unroll
        for (int j = 0; j < 4; j++)
            #pragma unroll
            for (int v = 0; v < 4; v++) acc[i][j][v] = 0.0f;

    load(0, 0);
    load(1, 1);

    for (int seg = 0; seg < NSEG; ++seg) {
        CP_WAIT(1);
        __syncthreads();
        load(seg + 2, (seg + 2) % 3);

        uint32_t ab = sb + (seg % 3) * STAGEB, bb = ab + TILEB;
        #pragma unroll
        for (int ki = 0; ki < 2; ki++) {
            uint32_t a[4][4];
            #pragma unroll
            for (int ni = 0; ni < 4; ni++) {
                int row = wn * 64 + ni * 16 + (lane & 15);
                int cc  = ki * 2 + (lane >> 4);
                uint32_t ad = ab + row * PITCH + cc * 16;
                asm volatile("ldmatrix.sync.aligned.m8n8.x4.shared.b16 {%0,%1,%2,%3}, [%4];"
                    : "=r"(a[ni][0]), "=r"(a[ni][1]), "=r"(a[ni][2]), "=r"(a[ni][3])
                    : "r"(ad));
            }
            uint32_t b[4][2];
            #pragma unroll
            for (int mi2 = 0; mi2 < 2; mi2++) {
                int row = wm * 32 + mi2 * 16 + (lane & 7) + ((lane >> 4) << 3);
                int cc  = ki * 2 + ((lane >> 3) & 1);
                uint32_t bd = bb + row * PITCH + cc * 16;
                uint32_t r0, r1, r2, r3;
                asm volatile("ldmatrix.sync.aligned.m8n8.x4.shared.b16 {%0,%1,%2,%3}, [%4];"
                    : "=r"(r0), "=r"(r1), "=r"(r2), "=r"(r3) : "r"(bd));
                b[mi2*2+0][0] = r0; b[mi2*2+0][1] = r1;
                b[mi2*2+1][0] = r2; b[mi2*2+1][1] = r3;
            }
            #pragma unroll
            for (int ni = 0; ni < 4; ni++)
                #pragma unroll
                for (int mi = 0; mi < 4; mi++)
                    mma_f16(acc[ni][mi], a[ni], b[mi]);
        }
    }

    // epilogue: BN affine + store [n][m] (float2, 32B-sector coalesced)
    const int group = lane >> 2, tig = lane & 3;
    #pragma unroll
    for (int mi = 0; mi < 4; mi++) {
        int m = m0 + wm * 32 + mi * 8 + tig * 2;
        float2 al = *(const float2*)&alpha[m];
        float2 of = *(const float2*)&offv[m];
        float2 be = *(const float2*)&beta[m];
        #pragma unroll
        for (int ni = 0; ni < 4; ni++)
            #pragma unroll
            for (int v = 0; v < 2; v++) {
                int n = n0 + wn * 64 + ni * 16 + group + v * 8;
                float2 val;
                val.x = al.x * (acc[ni][mi][v*2+0] + of.x) + be.x;
                val.y = al.y * (acc[ni][mi][v*2+1] + of.y) + be.y;
                *(float2*)&Y[((size_t)tbz * N_ + n) * Mtot + m] = val;
            }
    }
}

// ---------------- LIF kernels ------------------------------------------------
__global__ void lif_inplace(float* __restrict__ y, size_t S, float vth)
{
    size_t i = (size_t)blockIdx.x * blockDim.x + threadIdx.x;
    if (i >= S) return;
    float v = 0.0f;
    #pragma unroll
    for (int t = 0; t < T_; t++) {
        size_t idx = (size_t)t * S + i;
        float xx = y[idx];
        v = v + (xx - v) * 0.5f;
        float s = (v >= vth) ? 1.0f : 0.0f;
        y[idx] = s;
        if (s != 0.0f) v = 0.0f;
    }
}
__global__ void lif_to_half(const float* __restrict__ y, __half* __restrict__ o,
                            size_t S, float vth)
{
    size_t i = (size_t)blockIdx.x * blockDim.x + threadIdx.x;
    if (i >= S) return;
    float v = 0.0f;
    #pragma unroll
    for (int t = 0; t < T_; t++) {
        size_t idx = (size_t)t * S + i;
        float xx = y[idx];
        v = v + (xx - v) * 0.5f;
        float s = (v >= vth) ? 1.0f : 0.0f;
        o[idx] = __float2half_rn(s);
        if (s != 0.0f) v = 0.0f;
    }
}
// x1 = xt + spike(p); write x1 and its fp16 2-split
__global__ void lif_add_split(const float* __restrict__ p, size_t S)
{
    size_t i = (size_t)blockIdx.x * blockDim.x + threadIdx.x;
    if (i >= S) return;
    float v = 0.0f;
    #pragma unroll
    for (int t = 0; t < T_; t++) {
        size_t idx = (size_t)t * S + i;
        float xx = p[idx];
        v = v + (xx - v) * 0.5f;
        float s = (v >= 1.0f) ? 1.0f : 0.0f;
        float x1 = g_xt[idx] + s;
        g_x1[idx] = x1;
        split2h(x1, g_ps[0][idx], g_ps[1][idx]);
        if (s != 0.0f) v = 0.0f;
    }
}
// out[t,b,c,n] = x1 + spike(y2); internal buffers are [tb][n][c]
__global__ void lif_final(float* __restrict__ out, size_t S)
{
    size_t i = (size_t)blockIdx.x * blockDim.x + threadIdx.x;
    if (i >= S) return;
    int b = (int)(i / ((size_t)N_ * C_));
    int r = (int)(i % ((size_t)N_ * C_));
    int n = r >> 8, c = r & 255;
    float v = 0.0f;
    #pragma unroll
    for (int t = 0; t < T_; t++) {
        size_t idx = (size_t)t * S + i;
        float xx = g_y2[idx];
        v = v + (xx - v) * 0.5f;
        float s = (v >= 1.0f) ? 1.0f : 0.0f;
        out[(((size_t)t * B_ + b) * C_ + c) * N_ + n] = g_x1[idx] + s;
        if (s != 0.0f) v = 0.0f;
    }
}

// ---------------- attention (exact integer-valued fp32) ----------------------
__global__ __launch_bounds__(256) void attn_kernel()
{
    int h  = blockIdx.x & 7;
    int tb = blockIdx.x >> 3;
    const float* base = g_qkv + (size_t)tb * N_ * 768;

    __shared__ float ks[128][33];
    __shared__ float vs[128][36];
    __shared__ float kvs[32][33];

    int tid = threadIdx.x;
    int d  = tid >> 3;
    int e4 = (tid & 7) * 4;
    float acc[4] = {0.f, 0.f, 0.f, 0.f};

    for (int n0 = 0; n0 < N_; n0 += 128) {
        for (int i = tid; i < 128 * 32; i += 256) {
            int nl = i >> 5, dd = i & 31;
            const float* row = base + (size_t)(n0 + nl) * 768 + h * 32;
            ks[nl][dd] = row[256 + dd];
            vs[nl][dd] = row[512 + dd];
        }
        __syncthreads();
        for (int n = 0; n < 128; n++) {
            float kd = ks[n][d];
            float4 vv = *(const float4*)&vs[n][e4];
            acc[0] += kd * vv.x; acc[1] += kd * vv.y;
            acc[2] += kd * vv.z; acc[3] += kd * vv.w;
        }
        __syncthreads();
    }
    kvs[d][e4+0] = acc[0]; kvs[d][e4+1] = acc[1];
    kvs[d][e4+2] = acc[2]; kvs[d][e4+3] = acc[3];
    __syncthreads();

    for (int n = tid; n < N_; n += 256) {
        const float* qrow = base + (size_t)n * 768 + h * 32;
        float a[32];
        #pragma unroll
        for (int e = 0; e < 32; e++) a[e] = 0.0f;
        #pragma unroll
        for (int dd = 0; dd < 32; dd++) {
            if (qrow[dd] != 0.0f) {
                #pragma unroll
                for (int e = 0; e < 32; e++) a[e] += kvs[dd][e];
            }
        }
        float* ao = g_a + ((size_t)tb * N_ + n) * C_ + h * 32;
        #pragma unroll
        for (int e = 0; e < 32; e += 4) {
            float4 w;
            w.x = a[e]*0.125f; w.y = a[e+1]*0.125f;
            w.z = a[e+2]*0.125f; w.w = a[e+3]*0.125f;
            *(float4*)(ao + e) = w;
        }
    }
}

// ---------------- launch -----------------------------------------------------
extern "C" void kernel_launch(void* const* d_in, const int* in_sizes, int n_in,
                              void* d_out, int out_size)
{
    const float* x       = (const float*)d_in[0];
    const float* wq      = (const float*)d_in[2];
    const float* bn_q    = (const float*)d_in[3];
    const float* wk      = (const float*)d_in[4];
    const float* bn_k    = (const float*)d_in[5];
    const float* wv      = (const float*)d_in[6];
    const float* bn_v    = (const float*)d_in[7];
    const float* w_proj  = (const float*)d_in[8];
    const float* b_proj  = (const float*)d_in[9];
    const float* bn_proj = (const float*)d_in[10];
    const float* w_fc1   = (const float*)d_in[11];
    const float* b_fc1   = (const float*)d_in[12];
    const float* bn_fc1  = (const float*)d_in[13];
    const float* w_fc2   = (const float*)d_in[14];
    const float* b_fc2   = (const float*)d_in[15];
    const float* bn_fc2  = (const float*)d_in[16];
    float* out = (float*)d_out;

    __half *wr, *xsp, *ps, *wpb, *wf2b, *ab, *h1b;
    float *qkv, *a, *p, *h1, *y2, *al, *of, *be;
    cudaGetSymbolAddress((void**)&wr,   g_wr);
    cudaGetSymbolAddress((void**)&wpb,  g_wpb);
    cudaGetSymbolAddress((void**)&wf2b, g_wf2b);
    cudaGetSymbolAddress((void**)&xsp,  g_xsp);
    cudaGetSymbolAddress((void**)&ps,   g_ps);
    cudaGetSymbolAddress((void**)&ab,   g_ab);
    cudaGetSymbolAddress((void**)&h1b,  g_h1b);
    cudaGetSymbolAddress((void**)&qkv,  g_qkv);
    cudaGetSymbolAddress((void**)&a,    g_a);
    cudaGetSymbolAddress((void**)&p,    g_p);
    cudaGetSymbolAddress((void**)&h1,   g_h1);
    cudaGetSymbolAddress((void**)&y2,   g_y2);
    cudaGetSymbolAddress((void**)&al,   g_alpha);
    cudaGetSymbolAddress((void**)&of,   g_off);
    cudaGetSymbolAddress((void**)&be,   g_beta);

    const int SMEM = 3 * 20480;   // 61440
    cudaFuncSetAttribute(gemm_mma<256,3>,
                         cudaFuncAttributeMaxDynamicSharedMemorySize, SMEM);
    cudaFuncSetAttribute(gemm_mma<256,2>,
                         cudaFuncAttributeMaxDynamicSharedMemorySize, SMEM);
    cudaFuncSetAttribute(gemm_mma<1024,2>,
                         cudaFuncAttributeMaxDynamicSharedMemorySize, SMEM);

    prep_aff<<<1, 256>>>(bn_q, bn_k, bn_v, b_proj, bn_proj, b_fc1, bn_fc1, b_fc2, bn_fc2);
    prep_w_real<<<(WR_SZ + 255)/256, 256>>>(wq, wk, wv, w_fc1);
    prep_w_bin<<<(65536 + 262144 + 255)/256, 256>>>(w_proj, w_fc2);
    transpose_split<<<dim3(8, 32, TB_), 256>>>(x);

    // qkv: M=768, fp16 3-term (real input)
    gemm_mma<256,3><<<dim3(8, 6, TB_), 256, SMEM>>>(
        xsp, TCN, wr, WR_SZ, qkv, 768, al + AOFF_QKV, of + AOFF_QKV, be + AOFF_QKV);
    lif_inplace<<<(int)(S_QKV/256), 256>>>(qkv, S_QKV, 1.0f);

    attn_kernel<<<TB_ * HEADS_, 256>>>();
    lif_to_half<<<(int)(S_C/256), 256>>>(a, ab, S_C, 0.5f);

    // proj: M=256, fp16 2-term (binary input)
    gemm_mma<256,2><<<dim3(8, 2, TB_), 256, SMEM>>>(
        ab, 0, wpb, 65536, p, 256, al + AOFF_P, of + AOFF_P, be + AOFF_P);
    lif_add_split<<<(int)(S_C/256), 256>>>(p, S_C);

    // fc1: M=1024, fp16 3-term (real input), weights at rows 768..1791
    gemm_mma<256,3><<<dim3(8, 8, TB_), 256, SMEM>>>(
        ps, TCN, wr + 768*256, WR_SZ, h1, 1024, al + AOFF_F1, of + AOFF_F1, be + AOFF_F1);
    lif_to_half<<<(int)(S_H/256), 256>>>(h1, h1b, S_H, 1.0f);

    // fc2: M=256, K=1024, fp16 2-term (binary input)
    gemm_mma<1024,2><<<dim3(8, 2, TB_), 256, SMEM>>>(
        h1b, 0, wf2b, 262144, y2, 256, al + AOFF_F2, of + AOFF_F2, be + AOFF_F2);
    lif_final<<<(int)(S_C/256), 256>>>(out, S_C);
}